// round 1
// baseline (speedup 1.0000x reference)
#include <cuda_runtime.h>

#define EMB   1024
#define NH    16
#define HD    64
#define BATCH 4
#define SEQ   1024
#define MROWS (BATCH*SEQ)   // 4096
#define BH    (BATCH*NH)    // 64

// Scratch (device globals — allocation-free rule)
__device__ float g_Qre[(size_t)BH*SEQ*HD];     // Q+P, head-split (16 MB)
__device__ float g_Kre[(size_t)BH*SEQ*HD];     // K+P
__device__ float g_V  [(size_t)BH*SEQ*HD];     // V+P
__device__ float g_Im [(size_t)BH*SEQ*HD];     // Im head-split
__device__ float g_scores[(size_t)BH*SEQ*SEQ]; // 256 MB
__device__ float g_attn[(size_t)MROWS*EMB];    // merged attention output (16 MB)

// ---------------------------------------------------------------------------
// Kernel 1: QKV projections, fused head-split + bias + pos_enc add.
// C[4096,1024] = Re @ W ; epilogue scatters to (b,h,s,d) layout.
// blockIdx.z selects Q/K/V. 128x128 tile, BK=8, 256 thr, 8x8 microtile.
// ---------------------------------------------------------------------------
__global__ __launch_bounds__(256) void qkv_kernel(
    const float* __restrict__ Re, const float* __restrict__ pos,
    const float* __restrict__ Wq, const float* __restrict__ bq,
    const float* __restrict__ Wk, const float* __restrict__ bk,
    const float* __restrict__ Wv, const float* __restrict__ bv)
{
    const int which = blockIdx.z;
    const float* W    = (which == 0) ? Wq : (which == 1) ? Wk : Wv;
    const float* bias = (which == 0) ? bq : (which == 1) ? bk : bv;
    float* out        = (which == 0) ? g_Qre : (which == 1) ? g_Kre : g_V;

    __shared__ float As[8][129];
    __shared__ float Bs[8][128];

    const int bm = blockIdx.y * 128;
    const int bn = blockIdx.x * 128;
    const int t  = threadIdx.x;
    const int tx = t & 15, ty = t >> 4;

    float acc[8][8];
    #pragma unroll
    for (int i = 0; i < 8; i++)
        #pragma unroll
        for (int j = 0; j < 8; j++) acc[i][j] = 0.f;

    for (int k0 = 0; k0 < EMB; k0 += 8) {
        #pragma unroll
        for (int i = 0; i < 4; i++) {
            int e = t + 256 * i;
            int row = e >> 3, col = e & 7;
            As[col][row] = Re[(size_t)(bm + row) * EMB + k0 + col];
        }
        #pragma unroll
        for (int i = 0; i < 4; i++) {
            int e = t + 256 * i;
            int row = e >> 7, col = e & 127;
            Bs[row][col] = W[(size_t)(k0 + row) * EMB + bn + col];
        }
        __syncthreads();
        #pragma unroll
        for (int kk = 0; kk < 8; kk++) {
            float a[8], b[8];
            #pragma unroll
            for (int i = 0; i < 8; i++) a[i] = As[kk][ty * 8 + i];
            #pragma unroll
            for (int j = 0; j < 8; j++) b[j] = Bs[kk][tx * 8 + j];
            #pragma unroll
            for (int i = 0; i < 8; i++)
                #pragma unroll
                for (int j = 0; j < 8; j++) acc[i][j] += a[i] * b[j];
        }
        __syncthreads();
    }

    #pragma unroll
    for (int i = 0; i < 8; i++) {
        int m = bm + ty * 8 + i;
        int b = m >> 10, s = m & 1023;
        #pragma unroll
        for (int j = 0; j < 8; j++) {
            int n = bn + tx * 8 + j;
            int h = n >> 6, d = n & 63;
            float v = acc[i][j] + bias[n] + pos[(size_t)m * HD + d];
            out[(((size_t)(b * NH + h) * SEQ) + s) * HD + d] = v;
        }
    }
}

// ---------------------------------------------------------------------------
// Kernel 2: head-split of Im into (b,h,s,d)
// ---------------------------------------------------------------------------
__global__ __launch_bounds__(256) void imsplit_kernel(const float* __restrict__ Im)
{
    int gid = blockIdx.x * 256 + threadIdx.x;            // 0 .. 4194303
    int d = gid & 63;
    int s = (gid >> 6) & 1023;
    int h = (gid >> 16) & 15;
    int b = gid >> 20;
    g_Im[gid] = Im[((size_t)((b << 10) + s)) * EMB + (h << 6) + d];
}

// ---------------------------------------------------------------------------
// Kernel 3: scores[bh] = ([Q+P | Im] @ [K+P | Im]^T) / 32   (K-dim = 128)
// per (b,h): M=N=1024. 128x128 tile, BK=8.
// ---------------------------------------------------------------------------
__global__ __launch_bounds__(256) void scores_kernel()
{
    const int bh = blockIdx.z;
    const float* Qb = g_Qre + (size_t)bh * SEQ * HD;
    const float* Kb = g_Kre + (size_t)bh * SEQ * HD;
    const float* Ib = g_Im  + (size_t)bh * SEQ * HD;
    float* Sb = g_scores + (size_t)bh * SEQ * SEQ;

    __shared__ float As[8][129];
    __shared__ float Bs[8][129];

    const int bq = blockIdx.y * 128;
    const int bk = blockIdx.x * 128;
    const int t  = threadIdx.x;
    const int tx = t & 15, ty = t >> 4;

    float acc[8][8];
    #pragma unroll
    for (int i = 0; i < 8; i++)
        #pragma unroll
        for (int j = 0; j < 8; j++) acc[i][j] = 0.f;

    for (int k0 = 0; k0 < 128; k0 += 8) {
        const float* Aop = (k0 < 64) ? Qb : Ib;
        const float* Bop = (k0 < 64) ? Kb : Ib;
        const int dc = k0 & 63;
        #pragma unroll
        for (int i = 0; i < 4; i++) {
            int e = t + 256 * i;
            int row = e >> 3, col = e & 7;
            As[col][row] = Aop[(size_t)(bq + row) * HD + dc + col];
            Bs[col][row] = Bop[(size_t)(bk + row) * HD + dc + col];
        }
        __syncthreads();
        #pragma unroll
        for (int kk = 0; kk < 8; kk++) {
            float a[8], b[8];
            #pragma unroll
            for (int i = 0; i < 8; i++) a[i] = As[kk][ty * 8 + i];
            #pragma unroll
            for (int j = 0; j < 8; j++) b[j] = Bs[kk][tx * 8 + j];
            #pragma unroll
            for (int i = 0; i < 8; i++)
                #pragma unroll
                for (int j = 0; j < 8; j++) acc[i][j] += a[i] * b[j];
        }
        __syncthreads();
    }

    const float scale = 1.0f / 32.0f;   // 1/sqrt(1024)
    #pragma unroll
    for (int i = 0; i < 8; i++) {
        int q = bq + ty * 8 + i;
        #pragma unroll
        for (int j = 0; j < 8; j++) {
            int k = bk + tx * 8 + j;
            Sb[(size_t)q * SEQ + k] = acc[i][j] * scale;
        }
    }
}

// ---------------------------------------------------------------------------
// Kernel 4: row softmax over 1024 elems. One block (256 thr) per row.
// ---------------------------------------------------------------------------
__global__ __launch_bounds__(256) void softmax_kernel()
{
    const size_t row = blockIdx.x;
    float* p = g_scores + row * SEQ;
    const int t = threadIdx.x;

    float4 v = ((const float4*)p)[t];
    float m = fmaxf(fmaxf(v.x, v.y), fmaxf(v.z, v.w));
    #pragma unroll
    for (int o = 16; o > 0; o >>= 1) m = fmaxf(m, __shfl_xor_sync(0xffffffffu, m, o));

    __shared__ float red[8];
    if ((t & 31) == 0) red[t >> 5] = m;
    __syncthreads();
    float bm = red[0];
    #pragma unroll
    for (int i = 1; i < 8; i++) bm = fmaxf(bm, red[i]);
    __syncthreads();

    v.x = __expf(v.x - bm); v.y = __expf(v.y - bm);
    v.z = __expf(v.z - bm); v.w = __expf(v.w - bm);
    float s = v.x + v.y + v.z + v.w;
    #pragma unroll
    for (int o = 16; o > 0; o >>= 1) s += __shfl_xor_sync(0xffffffffu, s, o);
    if ((t & 31) == 0) red[t >> 5] = s;
    __syncthreads();
    float bs = 0.f;
    #pragma unroll
    for (int i = 0; i < 8; i++) bs += red[i];

    float inv = 1.0f / bs;
    v.x *= inv; v.y *= inv; v.z *= inv; v.w *= inv;
    ((float4*)p)[t] = v;
}

// ---------------------------------------------------------------------------
// Kernel 5: out[bh] = weights[bh] @ V[bh]  (M=1024, N=64, K=1024)
// 64x64 tile, BK=16, 256 thr, 4x4 microtile. Epilogue writes merged layout.
// ---------------------------------------------------------------------------
__global__ __launch_bounds__(256) void pv_kernel()
{
    const int bh = blockIdx.z;
    const int b = bh >> 4, h = bh & 15;
    const float* Wt = g_scores + (size_t)bh * SEQ * SEQ;
    const float* Vb = g_V      + (size_t)bh * SEQ * HD;

    __shared__ float As[16][65];
    __shared__ float Bs[16][68];

    const int bq = blockIdx.y * 64;
    const int t  = threadIdx.x;
    const int tx = t & 15, ty = t >> 4;

    float acc[4][4];
    #pragma unroll
    for (int i = 0; i < 4; i++)
        #pragma unroll
        for (int j = 0; j < 4; j++) acc[i][j] = 0.f;

    for (int k0 = 0; k0 < SEQ; k0 += 16) {
        #pragma unroll
        for (int i = 0; i < 4; i++) {
            int e = t + 256 * i;
            int row = e >> 4, col = e & 15;
            As[col][row] = Wt[(size_t)(bq + row) * SEQ + k0 + col];
        }
        #pragma unroll
        for (int i = 0; i < 4; i++) {
            int e = t + 256 * i;
            int row = e >> 6, col = e & 63;
            Bs[row][col] = Vb[(size_t)(k0 + row) * HD + col];
        }
        __syncthreads();
        #pragma unroll
        for (int kk = 0; kk < 16; kk++) {
            float a[4], bb[4];
            #pragma unroll
            for (int i = 0; i < 4; i++) a[i]  = As[kk][ty * 4 + i];
            #pragma unroll
            for (int j = 0; j < 4; j++) bb[j] = Bs[kk][tx * 4 + j];
            #pragma unroll
            for (int i = 0; i < 4; i++)
                #pragma unroll
                for (int j = 0; j < 4; j++) acc[i][j] += a[i] * bb[j];
        }
        __syncthreads();
    }

    #pragma unroll
    for (int i = 0; i < 4; i++) {
        int q = bq + ty * 4 + i;
        #pragma unroll
        for (int j = 0; j < 4; j++) {
            int d = tx * 4 + j;
            g_attn[(size_t)(b * SEQ + q) * EMB + h * HD + d] = acc[i][j];
        }
    }
}

// ---------------------------------------------------------------------------
// Kernel 6: final = g_attn(4096x1024) @ Wo + bo  -> d_out
// ---------------------------------------------------------------------------
__global__ __launch_bounds__(256) void final_kernel(
    const float* __restrict__ Wo, const float* __restrict__ bo,
    float* __restrict__ out)
{
    __shared__ float As[8][129];
    __shared__ float Bs[8][128];

    const int bm = blockIdx.y * 128;
    const int bn = blockIdx.x * 128;
    const int t  = threadIdx.x;
    const int tx = t & 15, ty = t >> 4;

    float acc[8][8];
    #pragma unroll
    for (int i = 0; i < 8; i++)
        #pragma unroll
        for (int j = 0; j < 8; j++) acc[i][j] = 0.f;

    for (int k0 = 0; k0 < EMB; k0 += 8) {
        #pragma unroll
        for (int i = 0; i < 4; i++) {
            int e = t + 256 * i;
            int row = e >> 3, col = e & 7;
            As[col][row] = g_attn[(size_t)(bm + row) * EMB + k0 + col];
        }
        #pragma unroll
        for (int i = 0; i < 4; i++) {
            int e = t + 256 * i;
            int row = e >> 7, col = e & 127;
            Bs[row][col] = Wo[(size_t)(k0 + row) * EMB + bn + col];
        }
        __syncthreads();
        #pragma unroll
        for (int kk = 0; kk < 8; kk++) {
            float a[8], b[8];
            #pragma unroll
            for (int i = 0; i < 8; i++) a[i] = As[kk][ty * 8 + i];
            #pragma unroll
            for (int j = 0; j < 8; j++) b[j] = Bs[kk][tx * 8 + j];
            #pragma unroll
            for (int i = 0; i < 8; i++)
                #pragma unroll
                for (int j = 0; j < 8; j++) acc[i][j] += a[i] * b[j];
        }
        __syncthreads();
    }

    #pragma unroll
    for (int i = 0; i < 8; i++) {
        int m = bm + ty * 8 + i;
        #pragma unroll
        for (int j = 0; j < 8; j++) {
            int n = bn + tx * 8 + j;
            out[(size_t)m * EMB + n] = acc[i][j] + bo[n];
        }
    }
}

// ---------------------------------------------------------------------------
extern "C" void kernel_launch(void* const* d_in, const int* in_sizes, int n_in,
                              void* d_out, int out_size)
{
    const float* Re  = (const float*)d_in[0];
    const float* Im  = (const float*)d_in[1];
    const float* pos = (const float*)d_in[2];
    const float* Wq  = (const float*)d_in[3];
    const float* bq  = (const float*)d_in[4];
    const float* Wk  = (const float*)d_in[5];
    const float* bk  = (const float*)d_in[6];
    const float* Wv  = (const float*)d_in[7];
    const float* bv  = (const float*)d_in[8];
    const float* Wo  = (const float*)d_in[9];
    const float* bo  = (const float*)d_in[10];
    float* out = (float*)d_out;

    qkv_kernel<<<dim3(8, 32, 3), 256>>>(Re, pos, Wq, bq, Wk, bk, Wv, bv);
    imsplit_kernel<<<16384, 256>>>(Im);
    scores_kernel<<<dim3(8, 8, 64), 256>>>();
    softmax_kernel<<<BH * SEQ, 256>>>();
    pv_kernel<<<dim3(1, 16, 64), 256>>>();
    final_kernel<<<dim3(8, 32, 1), 256>>>(Wo, bo, out);
}

// round 5
// speedup vs baseline: 2.9758x; 2.9758x over previous
#include <cuda_runtime.h>
#include <cuda_bf16.h>
#include <cstdint>
#include <cstddef>

#define EMB   1024
#define NH    16
#define HD    64
#define BATCH 4
#define SEQ   1024
#define BH    (BATCH*NH)    // 64
#define MROWS (BATCH*SEQ)   // 4096

typedef __nv_bfloat16 bf16;

// ---------------- scratch (device globals: allocation-free rule) ------------
__device__ bf16  g_ReH[(size_t)MROWS*EMB], g_ReL[(size_t)MROWS*EMB];
__device__ bf16  g_WTH[4][(size_t)EMB*EMB], g_WTL[4][(size_t)EMB*EMB];
__device__ bf16  g_QH[(size_t)BH*SEQ*HD], g_QL[(size_t)BH*SEQ*HD];
__device__ bf16  g_KH[(size_t)BH*SEQ*HD], g_KL[(size_t)BH*SEQ*HD];
__device__ bf16  g_ImH[(size_t)BH*SEQ*HD], g_ImL[(size_t)BH*SEQ*HD];
__device__ float g_V[(size_t)BH*SEQ*HD];
__device__ bf16  g_VTH[(size_t)BH*HD*SEQ], g_VTL[(size_t)BH*HD*SEQ];
__device__ float g_scores[(size_t)BH*SEQ*SEQ];                 // 256 MB
__device__ bf16  g_SWH[(size_t)BH*SEQ*SEQ], g_SWL[(size_t)BH*SEQ*SEQ];
__device__ bf16  g_attnH[(size_t)MROWS*EMB], g_attnL[(size_t)MROWS*EMB];

// ---------------- helpers ----------------------------------------------------
__device__ __forceinline__ void cp16(void* s, const void* g) {
    uint32_t a = (uint32_t)__cvta_generic_to_shared(s);
    asm volatile("cp.async.cg.shared.global [%0], [%1], 16;" :: "r"(a), "l"(g));
}
__device__ __forceinline__ void cp_commit() { asm volatile("cp.async.commit_group;"); }
template<int N> __device__ __forceinline__ void cp_wait() {
    asm volatile("cp.async.wait_group %0;" :: "n"(N));
}
__device__ __forceinline__ void mma_bf16(float c[4], const uint32_t a[4], const uint32_t b[2]) {
    asm volatile("mma.sync.aligned.m16n8k16.row.col.f32.bf16.bf16.f32 "
                 "{%0,%1,%2,%3}, {%4,%5,%6,%7}, {%8,%9}, {%0,%1,%2,%3};"
                 : "+f"(c[0]), "+f"(c[1]), "+f"(c[2]), "+f"(c[3])
                 : "r"(a[0]), "r"(a[1]), "r"(a[2]), "r"(a[3]),
                   "r"(b[0]), "r"(b[1]));
}
__device__ __forceinline__ uint32_t ld32s(const bf16* p) {
    return *(const uint32_t*)p;
}
// split v into hi/lo bf16 pair for two adjacent elements, vectorized store
__device__ __forceinline__ void store_split2(bf16* H, bf16* L, size_t idx,
                                             float v0, float v1) {
    bf16 h0 = __float2bfloat16(v0);
    bf16 h1 = __float2bfloat16(v1);
    bf16 l0 = __float2bfloat16(v0 - __bfloat162float(h0));
    bf16 l1 = __float2bfloat16(v1 - __bfloat162float(h1));
    *(__nv_bfloat162*)(H + idx) = __halves2bfloat162(h0, h1);
    *(__nv_bfloat162*)(L + idx) = __halves2bfloat162(l0, l1);
}
__device__ __forceinline__ void store_split1(bf16* H, bf16* L, size_t idx, float v) {
    bf16 h = __float2bfloat16(v);
    H[idx] = h;
    L[idx] = __float2bfloat16(v - __bfloat162float(h));
}

extern __shared__ char dsm[];

// ---------------- 3xBF16 tensor-core GEMM core -------------------------------
// C[TM x TN] = sum over NIT chunks of k=32:
//   (A_hi+A_lo)[TM x 32] * (B_hi+B_lo)[BROWS x 32]^T  (drop lo*lo)
// fa*/fb*(c,r): pointer to 32 contiguous bf16 k-values of row r, chunk c.
// st(r,c,v0,v1): store two adjacent output columns (c even).
// 256 threads, warp grid WM x WN, per-warp MT x NT fragments of 16x8.
template<int WM, int WN, int MT, int NT, int NIT, int BROWS,
         class FAH, class FAL, class FBH, class FBL, class ST>
__device__ __forceinline__ void gemm3bf(FAH fah, FAL fal, FBH fbh, FBL fbl, ST st) {
    constexpr int TM = WM * MT * 16;
    constexpr int LDH = 40;                          // halfs per row (80B, padded)
    constexpr int STAGE = (2 * TM + 2 * BROWS) * LDH;

    bf16* smh = (bf16*)dsm;
    const int t = threadIdx.x;
    const int w = t >> 5, lane = t & 31;
    const int g = lane >> 2, tig = lane & 3;
    const int wm = w / WN, wn = w % WN;

    auto load_tile = [&](int c, int s) {
        bf16* S = smh + s * STAGE;
        #pragma unroll
        for (int i = 0; i < TM * 4 / 256; i++) {
            int e = t + 256 * i, r = e >> 2, q = e & 3;
            cp16(&S[r * LDH + q * 8], fah(c, r) + q * 8);
        }
        #pragma unroll
        for (int i = 0; i < TM * 4 / 256; i++) {
            int e = t + 256 * i, r = e >> 2, q = e & 3;
            cp16(&S[TM * LDH + r * LDH + q * 8], fal(c, r) + q * 8);
        }
        #pragma unroll
        for (int i = 0; i < BROWS * 4 / 256; i++) {
            int e = t + 256 * i, r = e >> 2, q = e & 3;
            cp16(&S[2 * TM * LDH + r * LDH + q * 8], fbh(c, r) + q * 8);
        }
        #pragma unroll
        for (int i = 0; i < BROWS * 4 / 256; i++) {
            int e = t + 256 * i, r = e >> 2, q = e & 3;
            cp16(&S[2 * TM * LDH + BROWS * LDH + r * LDH + q * 8], fbl(c, r) + q * 8);
        }
        cp_commit();
    };

    float acc[MT][NT][4] = {};

    load_tile(0, 0);
    load_tile(1, 1);

    for (int it = 0; it < NIT; it++) {
        const int s = it & 1;
        if (it == NIT - 1) cp_wait<0>(); else cp_wait<1>();
        __syncthreads();

        const bf16* Ah = smh + s * STAGE + (wm * MT * 16) * LDH;
        const bf16* Al = Ah + TM * LDH;
        const bf16* Bh = smh + s * STAGE + 2 * TM * LDH + (wn * NT * 8) * LDH;
        const bf16* Bl = Bh + BROWS * LDH;

        #pragma unroll
        for (int kk = 0; kk < 2; kk++) {
            uint32_t ah[MT][4], al[MT][4], bh[NT][2], bl[NT][2];
            #pragma unroll
            for (int i = 0; i < MT; i++) {
                int base = (i * 16 + g) * LDH + kk * 16 + tig * 2;
                ah[i][0] = ld32s(Ah + base);
                ah[i][1] = ld32s(Ah + base + 8 * LDH);
                ah[i][2] = ld32s(Ah + base + 8);
                ah[i][3] = ld32s(Ah + base + 8 * LDH + 8);
                al[i][0] = ld32s(Al + base);
                al[i][1] = ld32s(Al + base + 8 * LDH);
                al[i][2] = ld32s(Al + base + 8);
                al[i][3] = ld32s(Al + base + 8 * LDH + 8);
            }
            #pragma unroll
            for (int j = 0; j < NT; j++) {
                int base = (j * 8 + g) * LDH + kk * 16 + tig * 2;
                bh[j][0] = ld32s(Bh + base);
                bh[j][1] = ld32s(Bh + base + 8);
                bl[j][0] = ld32s(Bl + base);
                bl[j][1] = ld32s(Bl + base + 8);
            }
            #pragma unroll
            for (int i = 0; i < MT; i++)
                #pragma unroll
                for (int j = 0; j < NT; j++) {
                    mma_bf16(acc[i][j], ah[i], bh[j]);
                    mma_bf16(acc[i][j], ah[i], bl[j]);
                    mma_bf16(acc[i][j], al[i], bh[j]);
                }
        }
        __syncthreads();
        if (it + 2 < NIT) load_tile(it + 2, s);
    }

    #pragma unroll
    for (int i = 0; i < MT; i++) {
        int r0 = wm * MT * 16 + i * 16 + g;
        #pragma unroll
        for (int j = 0; j < NT; j++) {
            int c0 = wn * NT * 8 + j * 8 + tig * 2;
            st(r0,     c0, acc[i][j][0], acc[i][j][1]);
            st(r0 + 8, c0, acc[i][j][2], acc[i][j][3]);
        }
    }
}

#define SMEM_128x128 ((2*128 + 2*128) * 40 * 2 * 2)   // 81920 B
#define SMEM_128x64  ((2*128 + 2*64)  * 40 * 2 * 2)   // 61440 B

// ---------------- elementwise prep kernels -----------------------------------
__global__ __launch_bounds__(256) void k_splitRe(const float* __restrict__ Re) {
    size_t gid = (size_t)blockIdx.x * 256 + threadIdx.x;     // per 2 elems
    float2 v = ((const float2*)Re)[gid];
    store_split2(g_ReH, g_ReL, gid * 2, v.x, v.y);
}

__global__ __launch_bounds__(256) void k_transW(
    const float* __restrict__ Wq, const float* __restrict__ Wk,
    const float* __restrict__ Wv, const float* __restrict__ Wo) {
    const float* src = (blockIdx.z == 0) ? Wq : (blockIdx.z == 1) ? Wk
                       : (blockIdx.z == 2) ? Wv : Wo;
    bf16* dH = g_WTH[blockIdx.z];
    bf16* dL = g_WTL[blockIdx.z];
    __shared__ float tile[32][33];
    int tx = threadIdx.x & 31, ty = threadIdx.x >> 5;
    int n0 = blockIdx.x * 32, k0 = blockIdx.y * 32;
    #pragma unroll
    for (int i = 0; i < 4; i++)
        tile[ty + i * 8][tx] = src[(size_t)(k0 + ty + i * 8) * EMB + n0 + tx];
    __syncthreads();
    #pragma unroll
    for (int i = 0; i < 4; i++)
        store_split1(dH, dL, (size_t)(n0 + ty + i * 8) * EMB + k0 + tx,
                     tile[tx][ty + i * 8]);
}

__global__ __launch_bounds__(256) void k_imsplit(const float* __restrict__ Im) {
    int gid = blockIdx.x * 256 + threadIdx.x;
    int d = gid & 63, s = (gid >> 6) & 1023, h = (gid >> 16) & 15, b = gid >> 20;
    float v = Im[((size_t)((b << 10) + s)) * EMB + (h << 6) + d];
    store_split1(g_ImH, g_ImL, gid, v);
}

__global__ __launch_bounds__(256) void k_transV() {
    const int bh = blockIdx.z;
    const float* src = g_V + (size_t)bh * SEQ * HD;
    bf16* dH = g_VTH + (size_t)bh * HD * SEQ;
    bf16* dL = g_VTL + (size_t)bh * HD * SEQ;
    __shared__ float tile[32][33];
    int tx = threadIdx.x & 31, ty = threadIdx.x >> 5;
    int s0 = blockIdx.x * 32, d0 = blockIdx.y * 32;
    #pragma unroll
    for (int i = 0; i < 4; i++)
        tile[ty + i * 8][tx] = src[(size_t)(s0 + ty + i * 8) * HD + d0 + tx];
    __syncthreads();
    #pragma unroll
    for (int i = 0; i < 4; i++)
        store_split1(dH, dL, (size_t)(d0 + ty + i * 8) * SEQ + s0 + tx,
                     tile[tx][ty + i * 8]);
}

// ---------------- GEMM 1: QKV projections ------------------------------------
__global__ __launch_bounds__(256) void k_qkv(
    const float* __restrict__ pos,
    const float* __restrict__ bq, const float* __restrict__ bk,
    const float* __restrict__ bv) {
    const int which = blockIdx.z;
    const bf16* WtH = g_WTH[which];
    const bf16* WtL = g_WTL[which];
    const float* bias = (which == 0) ? bq : (which == 1) ? bk : bv;
    const int bm = blockIdx.y * 128, bn = blockIdx.x * 128;

    gemm3bf<2, 4, 4, 4, 32, 128>(
        [&](int c, int r) { return g_ReH + (size_t)(bm + r) * EMB + c * 32; },
        [&](int c, int r) { return g_ReL + (size_t)(bm + r) * EMB + c * 32; },
        [&](int c, int r) { return WtH   + (size_t)(bn + r) * EMB + c * 32; },
        [&](int c, int r) { return WtL   + (size_t)(bn + r) * EMB + c * 32; },
        [&](int r, int c, float v0, float v1) {
            int m = bm + r, n = bn + c;
            int b = m >> 10, s = m & 1023, h = n >> 6, d = n & 63;
            size_t o = (((size_t)(b * NH + h)) * SEQ + s) * HD + d;
            const float* pp = pos + (size_t)m * HD + d;
            float x0 = v0 + bias[n] + pp[0];
            float x1 = v1 + bias[n + 1] + pp[1];
            if (which == 2) { float2 vv = {x0, x1}; *(float2*)&g_V[o] = vv; }
            else if (which == 0) store_split2(g_QH, g_QL, o, x0, x1);
            else                 store_split2(g_KH, g_KL, o, x0, x1);
        });
}

// ---------------- GEMM 2: scores = ([Q|Im] @ [K|Im]^T)/32 --------------------
__global__ __launch_bounds__(256) void k_scores() {
    const int bh = blockIdx.z;
    const size_t hb = (size_t)bh * SEQ * HD;
    float* Sb = g_scores + (size_t)bh * SEQ * SEQ;
    const int bq = blockIdx.y * 128, bk = blockIdx.x * 128;

    gemm3bf<2, 4, 4, 4, 4, 128>(
        [&](int c, int r) { const bf16* p = (c < 2) ? g_QH : g_ImH;
                            return p + hb + (size_t)(bq + r) * HD + (c & 1) * 32; },
        [&](int c, int r) { const bf16* p = (c < 2) ? g_QL : g_ImL;
                            return p + hb + (size_t)(bq + r) * HD + (c & 1) * 32; },
        [&](int c, int r) { const bf16* p = (c < 2) ? g_KH : g_ImH;
                            return p + hb + (size_t)(bk + r) * HD + (c & 1) * 32; },
        [&](int c, int r) { const bf16* p = (c < 2) ? g_KL : g_ImL;
                            return p + hb + (size_t)(bk + r) * HD + (c & 1) * 32; },
        [&](int r, int c, float v0, float v1) {
            float2 vv = { v0 * 0.03125f, v1 * 0.03125f };
            *(float2*)&Sb[(size_t)(bq + r) * SEQ + bk + c] = vv;
        });
}

// ---------------- softmax: scores -> split bf16 weights ----------------------
__global__ __launch_bounds__(256) void k_softmax() {
    const size_t row = blockIdx.x;
    const float* p = g_scores + row * SEQ;
    const int t = threadIdx.x;
    float4 v = ((const float4*)p)[t];
    float m = fmaxf(fmaxf(v.x, v.y), fmaxf(v.z, v.w));
    #pragma unroll
    for (int o = 16; o > 0; o >>= 1) m = fmaxf(m, __shfl_xor_sync(0xffffffffu, m, o));
    __shared__ float red[8];
    if ((t & 31) == 0) red[t >> 5] = m;
    __syncthreads();
    float bm = red[0];
    #pragma unroll
    for (int i = 1; i < 8; i++) bm = fmaxf(bm, red[i]);
    __syncthreads();
    v.x = __expf(v.x - bm); v.y = __expf(v.y - bm);
    v.z = __expf(v.z - bm); v.w = __expf(v.w - bm);
    float s = v.x + v.y + v.z + v.w;
    #pragma unroll
    for (int o = 16; o > 0; o >>= 1) s += __shfl_xor_sync(0xffffffffu, s, o);
    if ((t & 31) == 0) red[t >> 5] = s;
    __syncthreads();
    float bs = 0.f;
    #pragma unroll
    for (int i = 0; i < 8; i++) bs += red[i];
    float inv = 1.0f / bs;
    size_t o = row * SEQ + t * 4;
    store_split2(g_SWH, g_SWL, o,     v.x * inv, v.y * inv);
    store_split2(g_SWH, g_SWL, o + 2, v.z * inv, v.w * inv);
}

// ---------------- GEMM 3: attn = weights @ V ---------------------------------
__global__ __launch_bounds__(256) void k_pv() {
    const int bh = blockIdx.z, b = bh >> 4, h = bh & 15;
    const size_t wb = (size_t)bh * SEQ * SEQ;
    const size_t vb = (size_t)bh * HD * SEQ;
    const int bq = blockIdx.y * 128;

    gemm3bf<4, 2, 2, 4, 32, 64>(
        [&](int c, int r) { return g_SWH + wb + (size_t)(bq + r) * SEQ + c * 32; },
        [&](int c, int r) { return g_SWL + wb + (size_t)(bq + r) * SEQ + c * 32; },
        [&](int c, int r) { return g_VTH + vb + (size_t)r * SEQ + c * 32; },
        [&](int c, int r) { return g_VTL + vb + (size_t)r * SEQ + c * 32; },
        [&](int r, int c, float v0, float v1) {
            store_split2(g_attnH, g_attnL,
                         (size_t)(b * SEQ + bq + r) * EMB + h * HD + c, v0, v1);
        });
}

// ---------------- GEMM 4: out = attn @ Wo + bo -------------------------------
__global__ __launch_bounds__(256) void k_final(
    const float* __restrict__ bo, float* __restrict__ out) {
    const int bm = blockIdx.y * 128, bn = blockIdx.x * 128;
    const bf16* WtH = g_WTH[3];
    const bf16* WtL = g_WTL[3];

    gemm3bf<2, 4, 4, 4, 32, 128>(
        [&](int c, int r) { return g_attnH + (size_t)(bm + r) * EMB + c * 32; },
        [&](int c, int r) { return g_attnL + (size_t)(bm + r) * EMB + c * 32; },
        [&](int c, int r) { return WtH     + (size_t)(bn + r) * EMB + c * 32; },
        [&](int c, int r) { return WtL     + (size_t)(bn + r) * EMB + c * 32; },
        [&](int r, int c, float v0, float v1) {
            float2 vv = { v0 + bo[bn + c], v1 + bo[bn + c + 1] };
            *(float2*)&out[(size_t)(bm + r) * EMB + bn + c] = vv;
        });
}

// ---------------- launch -----------------------------------------------------
extern "C" void kernel_launch(void* const* d_in, const int* in_sizes, int n_in,
                              void* d_out, int out_size) {
    const float* Re  = (const float*)d_in[0];
    const float* Im  = (const float*)d_in[1];
    const float* pos = (const float*)d_in[2];
    const float* Wq  = (const float*)d_in[3];
    const float* bq  = (const float*)d_in[4];
    const float* Wk  = (const float*)d_in[5];
    const float* bk  = (const float*)d_in[6];
    const float* Wv  = (const float*)d_in[7];
    const float* bv  = (const float*)d_in[8];
    const float* Wo  = (const float*)d_in[9];
    const float* bo  = (const float*)d_in[10];
    float* out = (float*)d_out;

    static bool attr_done = false;
    if (!attr_done) {
        cudaFuncSetAttribute(k_qkv,    cudaFuncAttributeMaxDynamicSharedMemorySize, SMEM_128x128);
        cudaFuncSetAttribute(k_scores, cudaFuncAttributeMaxDynamicSharedMemorySize, SMEM_128x128);
        cudaFuncSetAttribute(k_pv,     cudaFuncAttributeMaxDynamicSharedMemorySize, SMEM_128x64);
        cudaFuncSetAttribute(k_final,  cudaFuncAttributeMaxDynamicSharedMemorySize, SMEM_128x128);
        attr_done = true;
    }

    k_splitRe<<<MROWS * EMB / 512, 256>>>(Re);
    k_transW <<<dim3(32, 32, 4), 256>>>(Wq, Wk, Wv, Wo);
    k_qkv    <<<dim3(8, 32, 3), 256, SMEM_128x128>>>(pos, bq, bk, bv);
    k_imsplit<<<16384, 256>>>(Im);
    k_transV <<<dim3(32, 2, BH), 256>>>();
    k_scores <<<dim3(8, 8, BH), 256, SMEM_128x128>>>();
    k_softmax<<<BH * SEQ, 256>>>();
    k_pv     <<<dim3(1, 8, BH), 256, SMEM_128x64>>>();
    k_final  <<<dim3(8, 32, 1), 256, SMEM_128x128>>>(bo, out);
}